// round 16
// baseline (speedup 1.0000x reference)
#include <cuda_runtime.h>
#include <cuda_fp16.h>
#include <cstdint>

// CapsuleLayer dynamic routing, 3 rounds.
// x: [512, 1152, 8] fp32   W: [10, 1152, 8, 16] fp32   out: [10, 512, 16] fp32
//
// R15 structure (proven 92.6us) + S0 fused into phase 1 in half2:
//   the v0 streamed pass is eliminated (routing passes 3 -> 2). s0 sums the
//   exact fp16 prior values as they are stored (2 HADD2 per (b,j), 8 regs),
//   reduced over rq with 24 shfl + 4 STS.128; v0 = squash(S0/NR) gathered
//   from per-warp fp32 partials. W stays converted-once (held wpk -- the
//   R13 JIT-cvt mistake is not repeated).
// W pre-pass (fp16): caps_Wh[n][g][ip][rq][oq] uint4 (16B = 8 halves):
//   halves 0..3 = W[g*8+rq][2ip][4oq..4oq+3], 4..7 = same at i=2ip+1.
//   Phase-1 warp instr (fixed ip) reads 512B contiguous -> 4 wf/LDG.128.
// Phase 1: warp = row-octet; lane = (rq 0..7, oq 0..3); b-pair split GEMM
//   (FMA2). Priors -> fp16 smem, PSTR=16, 16B-chunk XOR swizzle:
//   conflict-free STS.64 and LDS.128.
// Phase 2: 4 groups x 192 threads, 6 rows/thread, TWO streamed passes
//   (round1, round2), max-free softmax via ex2 (weight vector pre-scaled
//   by log2e). w = v0, then v0+v1 (logits additive in p).

#define NCAPS 10
#define NB    512
#define NR    1152
#define CI    8
#define CO    16
#define BT    4
#define NTHREADS 768
#define GROUPS (NB / BT)          // 128
#define TPB   192                 // threads per batch group (6 warps)
#define WPG   6
#define KPT   (NR / TPB)          // 6 rows per thread in routing
#define NWARP (NTHREADS / 32)     // 24
#define OCT   (NR / 8)            // 144 row-octets
#define JIT   (OCT / NWARP)       // 6 octets per warp
#define PSTR  16                  // halves per prior row (exact, swizzled)
#define LOG2E 1.4426950408889634f

// shared memory layout (bytes)
#define P_BYTES    (BT * NR * PSTR * 2)   // 147456 fp16 priors
#define SRED_OFF   P_BYTES
#define SRED_BYTES (BT * WPG * CO * 4)    // 1536
#define WRED_OFF   (SRED_OFF + SRED_BYTES)
#define WRED_BYTES (BT * WPG * 4)         // 96
#define VDOT_OFF   (WRED_OFF + WRED_BYTES)
#define VDOT_BYTES (BT * CO * 4)          // 256 (16B-aligned per group)
#define S0_OFF     (VDOT_OFF + VDOT_BYTES)
#define S0_BYTES   (NWARP * BT * CO * 4)  // 6144 per-warp fp32 S0 partials
#define SMEM_TOTAL (S0_OFF + S0_BYTES)

// repacked fp16 W: [NCAPS][OCT][4 ip][8 rq][4 oq] x 16B
__device__ __align__(16) uint4 caps_Wh[NCAPS * OCT * 4 * 32];

struct __align__(8) H4 { __half2 a, b; };
typedef unsigned long long u64;

__device__ __forceinline__ void fma2(u64& d, u64 a, u64 b) {
    asm("fma.rn.f32x2 %0, %1, %2, %0;" : "+l"(d) : "l"(a), "l"(b));
}
__device__ __forceinline__ u64 pack2(float x) {
    u64 r; asm("mov.b64 %0, {%1, %1};" : "=l"(r) : "f"(x)); return r;
}
__device__ __forceinline__ u64 packf2(float x, float y) {
    u64 r; asm("mov.b64 %0, {%1, %2};" : "=l"(r) : "f"(x), "f"(y)); return r;
}
__device__ __forceinline__ float2 unpack2(u64 v) {
    float2 f; asm("mov.b64 {%0, %1}, %2;" : "=f"(f.x), "=f"(f.y) : "l"(v));
    return f;
}
__device__ __forceinline__ u64 h2pk(uint32_t h) {    // half2 -> packed f32x2
    const float2 f = __half22float2(*(const __half2*)&h);
    return packf2(f.x, f.y);
}
__device__ __forceinline__ float ex2f(float x) {     // 2^x, one MUFU
    float r; asm("ex2.approx.ftz.f32 %0, %1;" : "=f"(r) : "f"(x)); return r;
}
__device__ __forceinline__ __half2 shfl_h2(__half2 v, int m) {
    const uint32_t u = __shfl_xor_sync(0xffffffffu, *(const uint32_t*)&v, m);
    return *(const __half2*)&u;
}
__device__ __forceinline__ void bar_group(int id) {
    asm volatile("bar.sync %0, %1;" :: "r"(id), "r"(TPB) : "memory");
}

// Load logical row r (16B-chunk swizzled) into f[16] via 2x LDS.128.
__device__ __forceinline__ void load_row_sw(const __half* pb, int r,
                                            float f[CO]) {
    const uint4* base = (const uint4*)(pb + (size_t)r * PSTR);
    const int s = (r >> 2) & 1;
    const uint4 u0 = base[s];        // logical chunk 0
    const uint4 u1 = base[s ^ 1];    // logical chunk 1
    const uint32_t hs[8] = {u0.x, u0.y, u0.z, u0.w, u1.x, u1.y, u1.z, u1.w};
    #pragma unroll
    for (int j = 0; j < 8; ++j) {
        const float2 ff = __half22float2(*(const __half2*)&hs[j]);
        f[2*j]   = ff.x;
        f[2*j+1] = ff.y;
    }
}

// Split-exchange reduce of S[16] over 32 lanes: 16 shfl total.
__device__ __forceinline__ void reduce_s16(float S[CO], int lane,
                                           float* sred_warp) {
    const bool h16 = lane & 16;
    #pragma unroll
    for (int j = 0; j < 8; ++j) {
        const float snd = h16 ? S[j] : S[j + 8];
        const float kp  = h16 ? S[j + 8] : S[j];
        S[j] = kp + __shfl_xor_sync(0xffffffffu, snd, 16);
    }
    const bool h8 = lane & 8;
    #pragma unroll
    for (int j = 0; j < 4; ++j) {
        const float snd = h8 ? S[j] : S[j + 4];
        const float kp  = h8 ? S[j + 4] : S[j];
        S[j] = kp + __shfl_xor_sync(0xffffffffu, snd, 8);
    }
    const bool h4 = lane & 4;
    #pragma unroll
    for (int j = 0; j < 2; ++j) {
        const float snd = h4 ? S[j] : S[j + 2];
        const float kp  = h4 ? S[j + 2] : S[j];
        S[j] = kp + __shfl_xor_sync(0xffffffffu, snd, 4);
    }
    const bool h2 = lane & 2;
    {
        const float snd = h2 ? S[0] : S[1];
        const float kp  = h2 ? S[1] : S[0];
        S[0] = kp + __shfl_xor_sync(0xffffffffu, snd, 2);
    }
    S[0] += __shfl_xor_sync(0xffffffffu, S[0], 1);
    const int comp = ((lane >> 4) & 1) * 8 + ((lane >> 3) & 1) * 4 +
                     ((lane >> 2) & 1) * 2 + ((lane >> 1) & 1);
    if (!(lane & 1)) sred_warp[comp] = S[0];
}

// ---------- W repack (fp32 -> fp16): 2 outputs per thread ----------
#define WTOTAL (NCAPS * OCT * 4 * 32)
__global__ void __launch_bounds__(256)
repack_w_kernel(const float* __restrict__ W) {
    const int tid = blockIdx.x * blockDim.x + threadIdx.x;
    #pragma unroll
    for (int h = 0; h < 2; ++h) {
        const int idx = tid + h * (WTOTAL / 2);
        const int oq = idx & 3;
        const int rq = (idx >> 2) & 7;
        const int ip = (idx >> 5) & 3;
        const int rb = idx >> 7;               // n*OCT + g
        const float* row = W + (size_t)(rb * 8 + rq) * 128;
        const float4 fe = *(const float4*)(row + (2*ip)     * 16 + 4*oq);
        const float4 fo = *(const float4*)(row + (2*ip + 1) * 16 + 4*oq);
        __half2 h0 = __floats2half2_rn(fe.x, fe.y);
        __half2 h1 = __floats2half2_rn(fe.z, fe.w);
        __half2 h2 = __floats2half2_rn(fo.x, fo.y);
        __half2 h3 = __floats2half2_rn(fo.z, fo.w);
        uint4 o;
        o.x = *(uint32_t*)&h0; o.y = *(uint32_t*)&h1;
        o.z = *(uint32_t*)&h2; o.w = *(uint32_t*)&h3;
        caps_Wh[idx] = o;
    }
}

__global__ void __launch_bounds__(NTHREADS, 1)
caps_kernel(const float* __restrict__ x,
            float* __restrict__ out) {
    extern __shared__ char smem[];
    __half* p    = (__half*)smem;
    float* sred  = (float*)(smem + SRED_OFF);
    float* wred  = (float*)(smem + WRED_OFF);
    float* vdot  = (float*)(smem + VDOT_OFF);
    float* s0red = (float*)(smem + S0_OFF);   // [warp][b][16 o] fp32

    const int n  = blockIdx.y;
    const int b0 = blockIdx.x * BT;
    const int t  = threadIdx.x;
    const int wid  = t >> 5;
    const int lane = t & 31;

    // ======== Phase 1: priors GEMM + fused half2 S0 ========
    // lane = (rq 0..7, oq 0..3)
    {
        const int rq = lane >> 2;
        const int oq = lane & 3;
        const int q  = oq >> 1;            // 16B chunk this lane's H4 lives in
        const int sub = (oq & 1) << 2;     // half-offset within chunk (halves)
        __half2 s0h[BT][2];
        #pragma unroll
        for (int b = 0; b < BT; ++b) {
            s0h[b][0] = __half2half2(__ushort_as_half(0));
            s0h[b][1] = __half2half2(__ushort_as_half(0));
        }
        #pragma unroll 1
        for (int j = 0; j < JIT; ++j) {
            const int g = wid + j * NWARP;
            const int r = g * 8 + rq;
            const int s = (r >> 2) & 1;
            const int choff = ((q ^ s) << 3) + sub;   // halves within row
            // W: 4 LDG.128, each warp-instr covers 512B contiguous
            const uint4* wh =
                caps_Wh + ((size_t)(n * OCT + g) * 4) * 32 + rq * 4 + oq;
            uint4 wc4[4];
            #pragma unroll
            for (int ip = 0; ip < 4; ++ip) wc4[ip] = wh[ip * 32];
            // convert once: 16 packed f32x2 (i ascending)
            u64 wpk[16];
            #pragma unroll
            for (int ip = 0; ip < 4; ++ip) {
                wpk[4*ip + 0] = h2pk(wc4[ip].x);   // i=2ip,   o0 o1
                wpk[4*ip + 1] = h2pk(wc4[ip].y);   // i=2ip,   o2 o3
                wpk[4*ip + 2] = h2pk(wc4[ip].z);   // i=2ip+1, o0 o1
                wpk[4*ip + 3] = h2pk(wc4[ip].w);   // i=2ip+1, o2 o3
            }

            // b-pair split keeps live registers bounded
            #pragma unroll
            for (int bp = 0; bp < 2; ++bp) {
                float xv[2][CI];
                #pragma unroll
                for (int bb = 0; bb < 2; ++bb) {
                    const int b = bp * 2 + bb;
                    const float4* xp =
                        (const float4*)(x + ((size_t)(b0 + b) * NR + r) * CI);
                    const float4 x0 = xp[0], x1 = xp[1];
                    xv[bb][0]=x0.x; xv[bb][1]=x0.y; xv[bb][2]=x0.z; xv[bb][3]=x0.w;
                    xv[bb][4]=x1.x; xv[bb][5]=x1.y; xv[bb][6]=x1.z; xv[bb][7]=x1.w;
                }
                u64 acc[2][2];
                acc[0][0]=0ull; acc[0][1]=0ull; acc[1][0]=0ull; acc[1][1]=0ull;
                #pragma unroll
                for (int i = 0; i < CI; ++i) {
                    const u64 wlo = wpk[(i >> 1) * 4 + (i & 1) * 2 + 0];
                    const u64 whi = wpk[(i >> 1) * 4 + (i & 1) * 2 + 1];
                    #pragma unroll
                    for (int bb = 0; bb < 2; ++bb) {
                        const u64 xx = pack2(xv[bb][i]);
                        fma2(acc[bb][0], xx, wlo);
                        fma2(acc[bb][1], xx, whi);
                    }
                }
                #pragma unroll
                for (int bb = 0; bb < 2; ++bb) {
                    const int b = bp * 2 + bb;
                    const float2 f0 = unpack2(acc[bb][0]);
                    const float2 f1 = unpack2(acc[bb][1]);
                    H4 h;
                    h.a = __floats2half2_rn(f0.x, f0.y);
                    h.b = __floats2half2_rn(f1.x, f1.y);
                    s0h[b][0] = __hadd2(s0h[b][0], h.a);   // fused S0
                    s0h[b][1] = __hadd2(s0h[b][1], h.b);
                    *(H4*)(p + (size_t)(b * NR + r) * PSTR + choff) = h;
                }
            }
        }
        // reduce s0 over rq (lane bits 2..4); rq==0 lanes store fp32 o-quad
        #pragma unroll
        for (int b = 0; b < BT; ++b) {
            #pragma unroll
            for (int m = 4; m <= 16; m <<= 1) {
                s0h[b][0] = __hadd2(s0h[b][0], shfl_h2(s0h[b][0], m));
                s0h[b][1] = __hadd2(s0h[b][1], shfl_h2(s0h[b][1], m));
            }
            if (rq == 0) {
                const float2 f0 = __half22float2(s0h[b][0]);
                const float2 f1 = __half22float2(s0h[b][1]);
                float4 o; o.x = f0.x; o.y = f0.y; o.z = f1.x; o.w = f1.y;
                *(float4*)(s0red + (wid * BT + b) * CO + oq * 4) = o;
            }
        }
    }
    __syncthreads();

    // ======== Phase 2: routing, 2 streamed passes ========
    const int b    = t / TPB;      // 0..3
    const int tb   = t % TPB;      // 0..191
    const int wl   = tb >> 5;      // warp in group 0..5
    const int bid  = b + 1;
    const __half* pb = p + (size_t)b * NR * PSTR;
    float* sredb = sred + b * WPG * CO;
    float* wredb = wred + b * WPG;
    float* vdotb = vdot + b * CO;

    // ---- v0 = squash(mean_r p_r) from fused S0 partials ----
    if (tb < CO) {
        float s = 0.f;
        #pragma unroll
        for (int w = 0; w < NWARP; ++w)
            s += s0red[(w * BT + b) * CO + tb];
        const float v = s * (1.0f / NR);
        float sq = v * v;
        #pragma unroll
        for (int off = 8; off; off >>= 1)
            sq += __shfl_xor_sync(0xffffu, sq, off);
        const float coef = sq / ((1.f + sq) * sqrtf(sq));
        vdotb[tb] = v * coef * LOG2E;       // pre-scaled for ex2
    }
    bar_group(bid);

    // ---- rounds 1 and 2: single fused streamed pass per round ----
    #pragma unroll
    for (int round = 0; round < 2; ++round) {
        // vd via 4x LDS.128 (holds log2e-scaled weight vector)
        float vd[CO];
        {
            const float4* vv = (const float4*)vdotb;
            #pragma unroll
            for (int q4 = 0; q4 < 4; ++q4) {
                const float4 v = vv[q4];
                vd[4*q4+0] = v.x; vd[4*q4+1] = v.y;
                vd[4*q4+2] = v.z; vd[4*q4+3] = v.w;
            }
        }

        float S[CO];
        #pragma unroll
        for (int o = 0; o < CO; ++o) S[o] = 0.f;
        float zloc = 0.f;

        #pragma unroll
        for (int k = 0; k < KPT; ++k) {
            float f[CO];
            load_row_sw(pb, tb + k * TPB, f);
            float a = 0.f;
            #pragma unroll
            for (int o = 0; o < CO; ++o) a += f[o] * vd[o];
            const float e = ex2f(a);        // a already in log2 units
            zloc += e;
            #pragma unroll
            for (int o = 0; o < CO; ++o) S[o] += e * f[o];
        }
        #pragma unroll
        for (int off = 16; off; off >>= 1)
            zloc += __shfl_xor_sync(0xffffffffu, zloc, off);
        if (lane == 0) wredb[wl] = zloc;
        reduce_s16(S, lane, sredb + wl * CO);
        bar_group(bid);

        if (tb < CO) {
            float s = 0.f;
            #pragma unroll
            for (int w = 0; w < WPG; ++w) s += sredb[w * CO + tb];
            float Z = wredb[0];
            #pragma unroll
            for (int w = 1; w < WPG; ++w) Z += wredb[w];
            const float v = s / Z;
            float sq = v * v;
            #pragma unroll
            for (int off = 8; off; off >>= 1)
                sq += __shfl_xor_sync(0xffffu, sq, off);
            const float coef = sq / ((1.f + sq) * sqrtf(sq));
            const float res = v * coef;
            if (round == 0)
                vdotb[tb] += res * LOG2E;               // w = v0 + v1 (scaled)
            else
                out[((size_t)n * NB + (b0 + b)) * CO + tb] = res;
        }
        bar_group(bid);
    }
}

extern "C" void kernel_launch(void* const* d_in, const int* in_sizes, int n_in,
                              void* d_out, int out_size) {
    (void)in_sizes; (void)n_in; (void)out_size;
    const float* x = (const float*)d_in[0];
    const float* W = (const float*)d_in[1];
    float* out = (float*)d_out;

    repack_w_kernel<<<WTOTAL / 2 / 256, 256>>>(W);

    cudaFuncSetAttribute(caps_kernel,
                         cudaFuncAttributeMaxDynamicSharedMemorySize, SMEM_TOTAL);
    dim3 grid(GROUPS, NCAPS);
    caps_kernel<<<grid, NTHREADS, SMEM_TOTAL>>>(x, out);
}

// round 17
// speedup vs baseline: 1.0307x; 1.0307x over previous
#include <cuda_runtime.h>
#include <cuda_fp16.h>
#include <cstdint>

// CapsuleLayer dynamic routing, 3 rounds.
// x: [512, 1152, 8] fp32   W: [10, 1152, 8, 16] fp32   out: [10, 512, 16] fp32
//
// R15 structure exactly (proven 92.6us; fused-S0 variants R13/R16 both
// regressed and are retired). Only change: repack_w does 4 outputs/thread
// with loads hoisted (MLP 8) -- it is replayed in every timed graph
// iteration and was latency-bound.
//
// W pre-pass (fp16): caps_Wh[n][g][ip][rq][oq] uint4 (16B = 8 halves):
//   halves 0..3 = W[g*8+rq][2ip][4oq..4oq+3], 4..7 = same at i=2ip+1.
//   Phase-1 warp instr (fixed ip) reads 512B contiguous -> 4 wf/LDG.128.
// Phase 1: warp = row-octet; lane = (rq 0..7, oq 0..3); W converted once to
//   16 packed f32x2 regs, b-pair split GEMM (FMA2). Priors -> fp16 smem,
//   PSTR=16, 16B-chunk XOR swizzle: conflict-free STS.64 and LDS.128.
// Phase 2: 4 groups x 192 threads, 6 rows/thread, three streamed passes
//   (v0 in half2 partials, round1, round2), max-free softmax via ex2
//   (weight vector pre-scaled by log2e). w = v0, then v0+v1.

#define NCAPS 10
#define NB    512
#define NR    1152
#define CI    8
#define CO    16
#define BT    4
#define NTHREADS 768
#define GROUPS (NB / BT)          // 128
#define TPB   192                 // threads per batch group (6 warps)
#define WPG   6
#define KPT   (NR / TPB)          // 6 rows per thread in routing
#define NWARP (NTHREADS / 32)     // 24
#define OCT   (NR / 8)            // 144 row-octets
#define JIT   (OCT / NWARP)       // 6 octets per warp
#define PSTR  16                  // halves per prior row (exact, swizzled)
#define LOG2E 1.4426950408889634f

// shared memory layout (bytes)
#define P_BYTES    (BT * NR * PSTR * 2)   // 147456 fp16 priors
#define SRED_OFF   P_BYTES
#define SRED_BYTES (BT * WPG * CO * 4)    // 1536
#define WRED_OFF   (SRED_OFF + SRED_BYTES)
#define WRED_BYTES (BT * WPG * 4)         // 96
#define VDOT_OFF   (WRED_OFF + WRED_BYTES)
#define VDOT_BYTES (BT * CO * 4)          // 256 (16B-aligned per group)
#define SMEM_TOTAL (VDOT_OFF + VDOT_BYTES)

// repacked fp16 W: [NCAPS][OCT][4 ip][8 rq][4 oq] x 16B
__device__ __align__(16) uint4 caps_Wh[NCAPS * OCT * 4 * 32];

struct __align__(8) H4 { __half2 a, b; };
typedef unsigned long long u64;

__device__ __forceinline__ void fma2(u64& d, u64 a, u64 b) {
    asm("fma.rn.f32x2 %0, %1, %2, %0;" : "+l"(d) : "l"(a), "l"(b));
}
__device__ __forceinline__ u64 pack2(float x) {
    u64 r; asm("mov.b64 %0, {%1, %1};" : "=l"(r) : "f"(x)); return r;
}
__device__ __forceinline__ u64 packf2(float x, float y) {
    u64 r; asm("mov.b64 %0, {%1, %2};" : "=l"(r) : "f"(x), "f"(y)); return r;
}
__device__ __forceinline__ float2 unpack2(u64 v) {
    float2 f; asm("mov.b64 {%0, %1}, %2;" : "=f"(f.x), "=f"(f.y) : "l"(v));
    return f;
}
__device__ __forceinline__ u64 h2pk(uint32_t h) {    // half2 -> packed f32x2
    const float2 f = __half22float2(*(const __half2*)&h);
    return packf2(f.x, f.y);
}
__device__ __forceinline__ float ex2f(float x) {     // 2^x, one MUFU
    float r; asm("ex2.approx.ftz.f32 %0, %1;" : "=f"(r) : "f"(x)); return r;
}
__device__ __forceinline__ void bar_group(int id) {
    asm volatile("bar.sync %0, %1;" :: "r"(id), "r"(TPB) : "memory");
}

// Load logical row r (16B-chunk swizzled) into f[16] via 2x LDS.128.
__device__ __forceinline__ void load_row_sw(const __half* pb, int r,
                                            float f[CO]) {
    const uint4* base = (const uint4*)(pb + (size_t)r * PSTR);
    const int s = (r >> 2) & 1;
    const uint4 u0 = base[s];        // logical chunk 0
    const uint4 u1 = base[s ^ 1];    // logical chunk 1
    const uint32_t hs[8] = {u0.x, u0.y, u0.z, u0.w, u1.x, u1.y, u1.z, u1.w};
    #pragma unroll
    for (int j = 0; j < 8; ++j) {
        const float2 ff = __half22float2(*(const __half2*)&hs[j]);
        f[2*j]   = ff.x;
        f[2*j+1] = ff.y;
    }
}

// Split-exchange reduce of S[16] over 32 lanes: 16 shfl total.
__device__ __forceinline__ void reduce_s16(float S[CO], int lane,
                                           float* sred_warp) {
    const bool h16 = lane & 16;
    #pragma unroll
    for (int j = 0; j < 8; ++j) {
        const float snd = h16 ? S[j] : S[j + 8];
        const float kp  = h16 ? S[j + 8] : S[j];
        S[j] = kp + __shfl_xor_sync(0xffffffffu, snd, 16);
    }
    const bool h8 = lane & 8;
    #pragma unroll
    for (int j = 0; j < 4; ++j) {
        const float snd = h8 ? S[j] : S[j + 4];
        const float kp  = h8 ? S[j + 4] : S[j];
        S[j] = kp + __shfl_xor_sync(0xffffffffu, snd, 8);
    }
    const bool h4 = lane & 4;
    #pragma unroll
    for (int j = 0; j < 2; ++j) {
        const float snd = h4 ? S[j] : S[j + 2];
        const float kp  = h4 ? S[j + 2] : S[j];
        S[j] = kp + __shfl_xor_sync(0xffffffffu, snd, 4);
    }
    const bool h2 = lane & 2;
    {
        const float snd = h2 ? S[0] : S[1];
        const float kp  = h2 ? S[1] : S[0];
        S[0] = kp + __shfl_xor_sync(0xffffffffu, snd, 2);
    }
    S[0] += __shfl_xor_sync(0xffffffffu, S[0], 1);
    const int comp = ((lane >> 4) & 1) * 8 + ((lane >> 3) & 1) * 4 +
                     ((lane >> 2) & 1) * 2 + ((lane >> 1) & 1);
    if (!(lane & 1)) sred_warp[comp] = S[0];
}

// ---------- W repack (fp32 -> fp16): 4 outputs/thread, loads hoisted ----
#define WTOTAL (NCAPS * OCT * 4 * 32)
__global__ void __launch_bounds__(256)
repack_w_kernel(const float* __restrict__ W) {
    const int tid = blockIdx.x * blockDim.x + threadIdx.x;
    float4 fe[4], fo[4];
    #pragma unroll
    for (int h = 0; h < 4; ++h) {
        const int idx = tid + h * (WTOTAL / 4);
        const int oq = idx & 3;
        const int rq = (idx >> 2) & 7;
        const int ip = (idx >> 5) & 3;
        const int rb = idx >> 7;               // n*OCT + g
        const float* row = W + (size_t)(rb * 8 + rq) * 128;
        fe[h] = *(const float4*)(row + (2*ip)     * 16 + 4*oq);
        fo[h] = *(const float4*)(row + (2*ip + 1) * 16 + 4*oq);
    }
    #pragma unroll
    for (int h = 0; h < 4; ++h) {
        const int idx = tid + h * (WTOTAL / 4);
        __half2 h0 = __floats2half2_rn(fe[h].x, fe[h].y);
        __half2 h1 = __floats2half2_rn(fe[h].z, fe[h].w);
        __half2 h2 = __floats2half2_rn(fo[h].x, fo[h].y);
        __half2 h3 = __floats2half2_rn(fo[h].z, fo[h].w);
        uint4 o;
        o.x = *(uint32_t*)&h0; o.y = *(uint32_t*)&h1;
        o.z = *(uint32_t*)&h2; o.w = *(uint32_t*)&h3;
        caps_Wh[idx] = o;
    }
}

__global__ void __launch_bounds__(NTHREADS, 1)
caps_kernel(const float* __restrict__ x,
            float* __restrict__ out) {
    extern __shared__ char smem[];
    __half* p   = (__half*)smem;
    float* sred = (float*)(smem + SRED_OFF);
    float* wred = (float*)(smem + WRED_OFF);
    float* vdot = (float*)(smem + VDOT_OFF);

    const int n  = blockIdx.y;
    const int b0 = blockIdx.x * BT;
    const int t  = threadIdx.x;
    const int wid  = t >> 5;
    const int lane = t & 31;

    // ======== Phase 1: priors GEMM (octet mapping, fp16 W) ========
    // lane = (rq 0..7, oq 0..3)
    {
        const int rq = lane >> 2;
        const int oq = lane & 3;
        const int q  = oq >> 1;            // 16B chunk this lane's H4 lives in
        const int sub = (oq & 1) << 2;     // half-offset within chunk (halves)
        #pragma unroll 1
        for (int j = 0; j < JIT; ++j) {
            const int g = wid + j * NWARP;
            const int r = g * 8 + rq;
            const int s = (r >> 2) & 1;
            const int choff = ((q ^ s) << 3) + sub;   // halves within row
            // W: 4 LDG.128, each warp-instr covers 512B contiguous
            const uint4* wh =
                caps_Wh + ((size_t)(n * OCT + g) * 4) * 32 + rq * 4 + oq;
            uint4 wc4[4];
            #pragma unroll
            for (int ip = 0; ip < 4; ++ip) wc4[ip] = wh[ip * 32];
            // convert once: 16 packed f32x2 (i ascending)
            u64 wpk[16];
            #pragma unroll
            for (int ip = 0; ip < 4; ++ip) {
                wpk[4*ip + 0] = h2pk(wc4[ip].x);   // i=2ip,   o0 o1
                wpk[4*ip + 1] = h2pk(wc4[ip].y);   // i=2ip,   o2 o3
                wpk[4*ip + 2] = h2pk(wc4[ip].z);   // i=2ip+1, o0 o1
                wpk[4*ip + 3] = h2pk(wc4[ip].w);   // i=2ip+1, o2 o3
            }

            // b-pair split keeps live registers bounded
            #pragma unroll
            for (int bp = 0; bp < 2; ++bp) {
                float xv[2][CI];
                #pragma unroll
                for (int bb = 0; bb < 2; ++bb) {
                    const int b = bp * 2 + bb;
                    const float4* xp =
                        (const float4*)(x + ((size_t)(b0 + b) * NR + r) * CI);
                    const float4 x0 = xp[0], x1 = xp[1];
                    xv[bb][0]=x0.x; xv[bb][1]=x0.y; xv[bb][2]=x0.z; xv[bb][3]=x0.w;
                    xv[bb][4]=x1.x; xv[bb][5]=x1.y; xv[bb][6]=x1.z; xv[bb][7]=x1.w;
                }
                u64 acc[2][2];
                acc[0][0]=0ull; acc[0][1]=0ull; acc[1][0]=0ull; acc[1][1]=0ull;
                #pragma unroll
                for (int i = 0; i < CI; ++i) {
                    const u64 wlo = wpk[(i >> 1) * 4 + (i & 1) * 2 + 0];
                    const u64 whi = wpk[(i >> 1) * 4 + (i & 1) * 2 + 1];
                    #pragma unroll
                    for (int bb = 0; bb < 2; ++bb) {
                        const u64 xx = pack2(xv[bb][i]);
                        fma2(acc[bb][0], xx, wlo);
                        fma2(acc[bb][1], xx, whi);
                    }
                }
                #pragma unroll
                for (int bb = 0; bb < 2; ++bb) {
                    const int b = bp * 2 + bb;
                    const float2 f0 = unpack2(acc[bb][0]);
                    const float2 f1 = unpack2(acc[bb][1]);
                    H4 h;
                    h.a = __floats2half2_rn(f0.x, f0.y);
                    h.b = __floats2half2_rn(f1.x, f1.y);
                    *(H4*)(p + (size_t)(b * NR + r) * PSTR + choff) = h;
                }
            }
        }
    }
    __syncthreads();

    // ======== Phase 2: routing, streamed rows, max-free softmax ========
    const int b    = t / TPB;      // 0..3
    const int tb   = t % TPB;      // 0..191
    const int wl   = tb >> 5;      // warp in group 0..5
    const int bid  = b + 1;
    const __half* pb = p + (size_t)b * NR * PSTR;
    float* sredb = sred + b * WPG * CO;
    float* wredb = wred + b * WPG;
    float* vdotb = vdot + b * CO;

    // ---- v0 = squash(mean_r p_r): one streamed pass, half2 partials ----
    {
        __half2 hacc[8];
        #pragma unroll
        for (int j = 0; j < 8; ++j) hacc[j] = __half2half2(__ushort_as_half(0));
        #pragma unroll
        for (int k = 0; k < KPT; ++k) {
            const int r = tb + k * TPB;
            const uint4* base = (const uint4*)(pb + (size_t)r * PSTR);
            const int s = (r >> 2) & 1;
            const uint4 u0 = base[s];
            const uint4 u1 = base[s ^ 1];
            hacc[0] = __hadd2(hacc[0], *(const __half2*)&u0.x);
            hacc[1] = __hadd2(hacc[1], *(const __half2*)&u0.y);
            hacc[2] = __hadd2(hacc[2], *(const __half2*)&u0.z);
            hacc[3] = __hadd2(hacc[3], *(const __half2*)&u0.w);
            hacc[4] = __hadd2(hacc[4], *(const __half2*)&u1.x);
            hacc[5] = __hadd2(hacc[5], *(const __half2*)&u1.y);
            hacc[6] = __hadd2(hacc[6], *(const __half2*)&u1.z);
            hacc[7] = __hadd2(hacc[7], *(const __half2*)&u1.w);
        }
        float S[CO];
        #pragma unroll
        for (int j = 0; j < 8; ++j) {
            const float2 ff = __half22float2(hacc[j]);
            S[2*j] = ff.x; S[2*j+1] = ff.y;
        }
        reduce_s16(S, lane, sredb + wl * CO);
        bar_group(bid);
        if (tb < CO) {
            float s = 0.f;
            #pragma unroll
            for (int w = 0; w < WPG; ++w) s += sredb[w * CO + tb];
            const float v = s * (1.0f / NR);
            float sq = v * v;
            #pragma unroll
            for (int off = 8; off; off >>= 1)
                sq += __shfl_xor_sync(0xffffu, sq, off);
            const float coef = sq / ((1.f + sq) * sqrtf(sq));
            vdotb[tb] = v * coef * LOG2E;   // pre-scaled for ex2
        }
        bar_group(bid);
    }

    // ---- rounds 1 and 2: single fused streamed pass per round ----
    #pragma unroll
    for (int round = 0; round < 2; ++round) {
        // vd via 4x LDS.128 (holds log2e-scaled weight vector)
        float vd[CO];
        {
            const float4* vv = (const float4*)vdotb;
            #pragma unroll
            for (int q4 = 0; q4 < 4; ++q4) {
                const float4 v = vv[q4];
                vd[4*q4+0] = v.x; vd[4*q4+1] = v.y;
                vd[4*q4+2] = v.z; vd[4*q4+3] = v.w;
            }
        }

        float S[CO];
        #pragma unroll
        for (int o = 0; o < CO; ++o) S[o] = 0.f;
        float zloc = 0.f;

        #pragma unroll
        for (int k = 0; k < KPT; ++k) {
            float f[CO];
            load_row_sw(pb, tb + k * TPB, f);
            float a = 0.f;
            #pragma unroll
            for (int o = 0; o < CO; ++o) a += f[o] * vd[o];
            const float e = ex2f(a);        // a already in log2 units
            zloc += e;
            #pragma unroll
            for (int o = 0; o < CO; ++o) S[o] += e * f[o];
        }
        #pragma unroll
        for (int off = 16; off; off >>= 1)
            zloc += __shfl_xor_sync(0xffffffffu, zloc, off);
        if (lane == 0) wredb[wl] = zloc;
        reduce_s16(S, lane, sredb + wl * CO);
        bar_group(bid);

        if (tb < CO) {
            float s = 0.f;
            #pragma unroll
            for (int w = 0; w < WPG; ++w) s += sredb[w * CO + tb];
            float Z = wredb[0];
            #pragma unroll
            for (int w = 1; w < WPG; ++w) Z += wredb[w];
            const float v = s / Z;
            float sq = v * v;
            #pragma unroll
            for (int off = 8; off; off >>= 1)
                sq += __shfl_xor_sync(0xffffu, sq, off);
            const float coef = sq / ((1.f + sq) * sqrtf(sq));
            const float res = v * coef;
            if (round == 0)
                vdotb[tb] += res * LOG2E;               // w = v0 + v1 (scaled)
            else
                out[((size_t)n * NB + (b0 + b)) * CO + tb] = res;
        }
        bar_group(bid);
    }
}

extern "C" void kernel_launch(void* const* d_in, const int* in_sizes, int n_in,
                              void* d_out, int out_size) {
    (void)in_sizes; (void)n_in; (void)out_size;
    const float* x = (const float*)d_in[0];
    const float* W = (const float*)d_in[1];
    float* out = (float*)d_out;

    repack_w_kernel<<<WTOTAL / 4 / 256, 256>>>(W);

    cudaFuncSetAttribute(caps_kernel,
                         cudaFuncAttributeMaxDynamicSharedMemorySize, SMEM_TOTAL);
    dim3 grid(GROUPS, NCAPS);
    caps_kernel<<<grid, NTHREADS, SMEM_TOTAL>>>(x, out);
}